// round 8
// baseline (speedup 1.0000x reference)
#include <cuda_runtime.h>
#include <cuda_bf16.h>
#include <math.h>

#define N_NODES 81
#define N_EDGES 1620
#define IN_DIM 10
#define HIDDEN 8192
#define ACTIONS 729

// Row chunks (of 128) of W1 read with default .ca loads (L2-resident part).
// 24 * 128 = 3072 rows = 96 MB pinned; remaining 160 MB streamed with __ldcs.
// Budget: 96 (W1 pin) + 24 (W2) + 2.7 (pre) ≈ 123 MB < 126 MB L2.
#define PIN_CHUNKS 24

// ---- scratch (no allocs allowed; __device__ globals) ----
__device__ float d_agg[N_NODES * IN_DIM];       // Â x  (input-space aggregate)
__device__ float d_pre[N_NODES * HIDDEN];       // relu(gcn) pre-LN
__device__ float d_mu[N_NODES];
__device__ float d_rinv[N_NODES];
__device__ float d_g[HIDDEN];                   // pooled vector
__device__ float d_y1[HIDDEN];                  // g @ W1 accumulator
__device__ float d_logits[736];                 // y1r @ W2 accumulator

// ============================================================
// K1: degrees, norms, input-space aggregation; zero accumulators
// edge_index dtype detected at runtime (int32 vs int64):
// int64 viewed as int32 pairs has all-zero high words (values < 81).
// ============================================================
__global__ void k_setup(const float* __restrict__ x,
                        const int* __restrict__ ei32) {
    __shared__ float s_deg[N_NODES];
    __shared__ float s_dinv[N_NODES];
    __shared__ float s_agg[N_NODES * IN_DIM];
    __shared__ int s_is64;
    int t = threadIdx.x;

    // zero the cross-launch accumulators (graph replays re-run this first)
    for (int i = t; i < HIDDEN; i += 256) d_y1[i] = 0.f;
    for (int i = t; i < 736; i += 256) d_logits[i] = 0.f;

    if (t == 0) {
        int any = 0;
        #pragma unroll 8
        for (int i = 0; i < 128; i++) any |= ei32[2 * i + 1];
        s_is64 = (any == 0) ? 1 : 0;   // all high words zero -> int64
    }
    if (t < N_NODES) s_deg[t] = 1.f;  // self-loop
    for (int i = t; i < N_NODES * IN_DIM; i += 256) s_agg[i] = 0.f;
    __syncthreads();
    const int is64 = s_is64;

    for (int e = t; e < N_EDGES; e += 256) {
        int d = is64 ? ei32[2 * (N_EDGES + e)] : ei32[N_EDGES + e];
        atomicAdd(&s_deg[d], 1.f);
    }
    __syncthreads();

    if (t < N_NODES) s_dinv[t] = rsqrtf(s_deg[t]);
    __syncthreads();

    for (int e = t; e < N_EDGES; e += 256) {
        int s = is64 ? ei32[2 * e] : ei32[e];
        int d = is64 ? ei32[2 * (N_EDGES + e)] : ei32[N_EDGES + e];
        float nm = s_dinv[s] * s_dinv[d];
        #pragma unroll
        for (int k = 0; k < IN_DIM; k++)
            atomicAdd(&s_agg[d * IN_DIM + k], nm * x[s * IN_DIM + k]);
    }
    if (t < N_NODES) {
        float nm = s_dinv[t] * s_dinv[t];  // self-loop message
        #pragma unroll
        for (int k = 0; k < IN_DIM; k++)
            atomicAdd(&s_agg[t * IN_DIM + k], nm * x[t * IN_DIM + k]);
    }
    __syncthreads();

    for (int i = t; i < N_NODES * IN_DIM; i += 256) d_agg[i] = s_agg[i];
}

// ============================================================
// K2: pre[n][j] = relu(agg[n] . W_gcn[:,j] + b_gcn[j])
//     one thread per hidden j, grid 32x256
// ============================================================
__global__ void __launch_bounds__(256) k_gcn(const float* __restrict__ Wg,
                                             const float* __restrict__ bg) {
    __shared__ float s_agg[N_NODES * IN_DIM];
    int t = threadIdx.x;
    for (int i = t; i < N_NODES * IN_DIM; i += 256) s_agg[i] = d_agg[i];
    __syncthreads();

    int j = blockIdx.x * 256 + t;
    float w[IN_DIM];
    #pragma unroll
    for (int k = 0; k < IN_DIM; k++) w[k] = Wg[k * HIDDEN + j];
    float bj = bg[j];

    for (int n = 0; n < N_NODES; n++) {
        float acc = bj;
        #pragma unroll
        for (int k = 0; k < IN_DIM; k++)
            acc = fmaf(s_agg[n * IN_DIM + k], w[k], acc);
        d_pre[n * HIDDEN + j] = fmaxf(acc, 0.f);
    }
}

// ============================================================
// K3: per-node LN stats; one block per node; warp-shuffle reduce
//     pre is L2-hot (just written) — reads come from L2.
// ============================================================
__global__ void __launch_bounds__(256) k_stats() {
    int n = blockIdx.x;
    int t = threadIdx.x;
    const float* row = d_pre + (size_t)n * HIDDEN;
    float s = 0.f, q = 0.f;
    #pragma unroll 8
    for (int j = t; j < HIDDEN; j += 256) {
        float p = row[j];
        s += p;
        q = fmaf(p, p, q);
    }
    // warp reduce
    #pragma unroll
    for (int o = 16; o > 0; o >>= 1) {
        s += __shfl_xor_sync(0xffffffffu, s, o);
        q += __shfl_xor_sync(0xffffffffu, q, o);
    }
    __shared__ float ws[8], wq[8];
    int w = t >> 5, l = t & 31;
    if (l == 0) { ws[w] = s; wq[w] = q; }
    __syncthreads();
    if (t == 0) {
        float S = 0.f, Q = 0.f;
        #pragma unroll
        for (int i = 0; i < 8; i++) { S += ws[i]; Q += wq[i]; }
        float mu = S * (1.f / HIDDEN);
        float var = Q * (1.f / HIDDEN) - mu * mu;
        d_mu[n] = mu;
        d_rinv[n] = rsqrtf(var + 1e-5f);
    }
}

// ============================================================
// K4: pooled vector
//   g[j] = ln_g[j]*(sum_n rinv_n*pre[n][j] - C) + 81*ln_b[j]
//   where C = sum_n rinv_n*mu_n
// ============================================================
__global__ void __launch_bounds__(256) k_pool(const float* __restrict__ lng,
                                              const float* __restrict__ lnb) {
    __shared__ float s_r[N_NODES];
    __shared__ float s_rm[N_NODES];
    int t = threadIdx.x;
    if (t < N_NODES) {
        float r = d_rinv[t];
        s_r[t] = r;
        s_rm[t] = r * d_mu[t];
    }
    __syncthreads();
    float C = 0.f;
    #pragma unroll
    for (int n = 0; n < N_NODES; n++) C += s_rm[n];

    int j = blockIdx.x * 256 + t;
    float acc = 0.f;
    #pragma unroll 8
    for (int n = 0; n < N_NODES; n++)
        acc = fmaf(s_r[n], d_pre[n * HIDDEN + j], acc);
    d_g[j] = lng[j] * (acc - C) + (float)N_NODES * lnb[j];
}

// ============================================================
// K5: y1 = g @ W1   (the 256MB matvec — the whole problem)
//   grid (8 i-chunks x 64 j-chunks), 256 threads.
//   Each thread: one float4 column, 128 rows; split-K via atomicAdd.
//   L2 residency split: first PIN_CHUNKS row-chunks use .ca loads
//   (stay L2-resident across graph replays); rest use __ldcs
//   (evict-first streaming, doesn't thrash the pinned part).
// ============================================================
__global__ void __launch_bounds__(256) k_mv1(const float* __restrict__ W1) {
    __shared__ float s_g[128];
    int t = threadIdx.x;
    int j0 = blockIdx.y * 128;
    if (t < 128) s_g[t] = d_g[j0 + t];
    __syncthreads();

    int i4 = blockIdx.x * 256 + t;               // float4 index in [0, 2048)
    const float4* W4 = (const float4*)W1;        // row stride = 2048 float4
    const float4* base = W4 + (size_t)j0 * (HIDDEN / 4) + i4;
    float4 acc = make_float4(0.f, 0.f, 0.f, 0.f);

    if (blockIdx.y < PIN_CHUNKS) {
        #pragma unroll 8
        for (int jj = 0; jj < 128; jj++) {
            float gv = s_g[jj];
            float4 w = base[(size_t)jj * (HIDDEN / 4)];
            acc.x = fmaf(gv, w.x, acc.x);
            acc.y = fmaf(gv, w.y, acc.y);
            acc.z = fmaf(gv, w.z, acc.z);
            acc.w = fmaf(gv, w.w, acc.w);
        }
    } else {
        #pragma unroll 8
        for (int jj = 0; jj < 128; jj++) {
            float gv = s_g[jj];
            float4 w = __ldcs(&base[(size_t)jj * (HIDDEN / 4)]);
            acc.x = fmaf(gv, w.x, acc.x);
            acc.y = fmaf(gv, w.y, acc.y);
            acc.z = fmaf(gv, w.z, acc.z);
            acc.w = fmaf(gv, w.w, acc.w);
        }
    }
    float* y = d_y1 + (size_t)i4 * 4;
    atomicAdd(y + 0, acc.x);
    atomicAdd(y + 1, acc.y);
    atomicAdd(y + 2, acc.z);
    atomicAdd(y + 3, acc.w);
}

// ============================================================
// K6: logits = relu(y1 + b1) @ W2   (24MB; keep .ca → L2-resident)
//   grid 128 i-chunks of 64; 736 threads (23 warps, 729 active)
// ============================================================
__global__ void __launch_bounds__(736) k_mv2(const float* __restrict__ W2,
                                             const float* __restrict__ b1) {
    __shared__ float s_y[64];
    int t = threadIdx.x;
    int i0 = blockIdx.x * 64;
    if (t < 64) {
        float v = d_y1[i0 + t] + b1[i0 + t];
        s_y[t] = fmaxf(v, 0.f);
    }
    __syncthreads();
    if (t < ACTIONS) {
        const float* w = W2 + (size_t)i0 * ACTIONS + t;
        float acc = 0.f;
        #pragma unroll 8
        for (int ii = 0; ii < 64; ii++)
            acc = fmaf(s_y[ii], __ldg(w + (size_t)ii * ACTIONS), acc);
        atomicAdd(&d_logits[t], acc);
    }
}

// ============================================================
// K7: add b2, log_softmax, write output
// ============================================================
__global__ void __launch_bounds__(1024) k_out(const float* __restrict__ b2,
                                              float* __restrict__ out) {
    __shared__ float sh[1024];
    int t = threadIdx.x;
    float l = (t < ACTIONS) ? d_logits[t] + b2[t] : -1e30f;
    sh[t] = l;
    __syncthreads();
    for (int s = 512; s > 0; s >>= 1) {
        if (t < s) sh[t] = fmaxf(sh[t], sh[t + s]);
        __syncthreads();
    }
    float m = sh[0];
    __syncthreads();
    float e = (t < ACTIONS) ? expf(l - m) : 0.f;
    sh[t] = e;
    __syncthreads();
    for (int s = 512; s > 0; s >>= 1) {
        if (t < s) sh[t] += sh[t + s];
        __syncthreads();
    }
    float lse = logf(sh[0]);
    if (t < ACTIONS) out[t] = l - m - lse;
}

// ============================================================
extern "C" void kernel_launch(void* const* d_in, const int* in_sizes, int n_in,
                              void* d_out, int out_size) {
    const float* x   = (const float*)d_in[0];
    const int*   ei  = (const int*)d_in[1];     // int32 or int64 (detected)
    const float* Wg  = (const float*)d_in[2];
    const float* bg  = (const float*)d_in[3];
    const float* lng = (const float*)d_in[4];
    const float* lnb = (const float*)d_in[5];
    const float* W1  = (const float*)d_in[6];
    const float* b1  = (const float*)d_in[7];
    const float* W2  = (const float*)d_in[8];
    const float* b2  = (const float*)d_in[9];
    float* out = (float*)d_out;

    k_setup<<<1, 256>>>(x, ei);
    k_gcn<<<32, 256>>>(Wg, bg);
    k_stats<<<N_NODES, 256>>>();
    k_pool<<<32, 256>>>(lng, lnb);
    k_mv1<<<dim3(8, 64), 256>>>(W1);
    k_mv2<<<128, 736>>>(W2, b1);
    k_out<<<1, 1024>>>(b2, out);
}